// round 8
// baseline (speedup 1.0000x reference)
#include <cuda_runtime.h>
#include <cuda_bf16.h>
#include <stdint.h>

#define THREADS 256
#define TM 64
#define APAD 40
#define BPAD 40
#define HP 264

// device scratch
__device__ __align__(16) __nv_bfloat16 g_Wt[256 * 512];   // [n][k] decoder weights, bf16
__device__ __align__(16) __nv_bfloat16 g_Wp2[256 * 256];  // [p*16+c][k] head weights, bf16
__device__ float g_sums[16];
__device__ float g_cnts[16];
__device__ int g_done;

// SMEM layout (bytes)
#define SM_A0 0
#define SM_A1 5120
#define SM_B0 10240
#define SM_B1 30720
#define SM_H 51200
#define SM_LG 84992
#define SM_BIAS 89344
#define SM_BPRED 90368
#define SM_EM 91392
#define SM_SPAIR 92928
#define SM_SLABEL 93184
#define SM_PSUM 93440
#define SM_PCNT 93504
#define SMEM_TOTAL 93568

__global__ void prep_kernel(const float* __restrict__ W1, const float* __restrict__ W2,
                            const float* __restrict__ Wp) {
  int i = blockIdx.x * blockDim.x + threadIdx.x;
  if (i < 256 * 512) {
    int n = i >> 9, k = i & 511;
    float v = (k < 256) ? W1[k * 256 + n] : W2[(k - 256) * 256 + n];
    g_Wt[n * 512 + k] = __float2bfloat16(v);
  }
  if (i < 256 * 256) {
    int col = i >> 8, k = i & 255;
    int p = col >> 4, c = col & 15;
    g_Wp2[col * 256 + k] = __float2bfloat16(Wp[p * 4096 + k * 16 + c]);
  }
  if (i < 16) { g_sums[i] = 0.f; g_cnts[i] = 0.f; }
  if (i == 0) g_done = 0;
}

__device__ __forceinline__ void mma16816(float* c, uint32_t a0, uint32_t a1, uint32_t a2,
                                         uint32_t a3, uint32_t b0, uint32_t b1) {
  asm volatile(
      "mma.sync.aligned.m16n8k16.row.col.f32.bf16.bf16.f32 "
      "{%0,%1,%2,%3}, {%4,%5,%6,%7}, {%8,%9}, {%0,%1,%2,%3};\n"
      : "+f"(c[0]), "+f"(c[1]), "+f"(c[2]), "+f"(c[3])
      : "r"(a0), "r"(a1), "r"(a2), "r"(a3), "r"(b0), "r"(b1));
}

__device__ __forceinline__ uint32_t s2u(const void* p) {
  uint32_t a;
  asm("{ .reg .u64 t; cvta.to.shared.u64 t, %1; cvt.u32.u64 %0, t; }" : "=r"(a) : "l"(p));
  return a;
}

__device__ __forceinline__ void cp16(uint32_t dst, const void* src) {
  asm volatile("cp.async.cg.shared.global [%0], [%1], 16;" ::"r"(dst), "l"(src) : "memory");
}
__device__ __forceinline__ void cp_commit() {
  asm volatile("cp.async.commit_group;" ::: "memory");
}
__device__ __forceinline__ void cp_wait0() {
  asm volatile("cp.async.wait_group 0;" ::: "memory");
}

__device__ __forceinline__ uint4 pack8(float4 a, float4 b) {
  __nv_bfloat162 p0 = __floats2bfloat162_rn(a.x, a.y);
  __nv_bfloat162 p1 = __floats2bfloat162_rn(a.z, a.w);
  __nv_bfloat162 p2 = __floats2bfloat162_rn(b.x, b.y);
  __nv_bfloat162 p3 = __floats2bfloat162_rn(b.z, b.w);
  uint4 u;
  u.x = *(uint32_t*)&p0; u.y = *(uint32_t*)&p1;
  u.z = *(uint32_t*)&p2; u.w = *(uint32_t*)&p3;
  return u;
}

// B chunk [256 rows][32 k] via cp.async: thread t -> row t, 4x16B
__device__ __forceinline__ void cpB(uint32_t su, uint32_t off, const __nv_bfloat16* src, int ldk,
                                    int koff, int t) {
  const __nv_bfloat16* s = src + t * ldk + koff;
  uint32_t d = su + off + t * (BPAD * 2);
  cp16(d, s);
  cp16(d + 16, s + 8);
  cp16(d + 32, s + 16);
  cp16(d + 48, s + 24);
}

__global__ __launch_bounds__(THREADS, 2)
void main_kernel(const float* __restrict__ h_src, const float* __restrict__ h_dst,
                 const float* __restrict__ b_dec, const float* __restrict__ b_pred,
                 const int* __restrict__ st, const int* __restrict__ dt,
                 const int* __restrict__ etc, const int* __restrict__ emap,
                 float* __restrict__ out, int E) {
  extern __shared__ __align__(16) char smem[];
  const int tid = threadIdx.x;
  const int warp = tid >> 5, lane = tid & 31;
  const int wm = warp & 1, wn = warp >> 1;  // 2 x 4 warp grid, warp tile 32m x 64n
  const long e0 = (long)blockIdx.x * TM;
  const uint32_t su = s2u(smem);

  float* bias = (float*)(smem + SM_BIAS);
  float* bpred = (float*)(smem + SM_BPRED);
  int* em = (int*)(smem + SM_EM);
  int* spair = (int*)(smem + SM_SPAIR);
  int* slabel = (int*)(smem + SM_SLABEL);
  float* psum = (float*)(smem + SM_PSUM);
  int* pcnt = (int*)(smem + SM_PCNT);
  float* Lg = (float*)(smem + SM_LG);

  // kick off B chunk 0 before anything else
  cpB(su, SM_B0, g_Wt, 512, 0, tid);
  cp_commit();

  for (int i = tid; i < 256; i += THREADS) { bias[i] = b_dec[i]; bpred[i] = b_pred[i]; }
  for (int i = tid; i < 384; i += THREADS) em[i] = emap[i];
  if (tid < 16) { psum[tid] = 0.f; pcnt[tid] = 0; }
  if (tid < 64) {
    long e = e0 + tid; if (e >= E) e = E - 1;
    int p = st[e] * 4 + dt[e];
    spair[tid] = p;
    slabel[tid] = em[p * 24 + etc[e]];  // em just written by this thread range pattern
  }
  // NOTE: em written by all threads striding; the tid<64 read above races. Redo safely:
  __syncthreads();
  if (tid < 64) {
    long e = e0 + tid; if (e >= E) e = E - 1;
    int p = st[e] * 4 + dt[e];
    spair[tid] = p;
    slabel[tid] = em[p * 24 + etc[e]];
  }

  const int ar = tid >> 2, ac = (tid & 3) * 8;  // A: 64 rows x 32 k, 8 floats/thread
  long ae = e0 + ar; if (ae >= E) ae = E - 1;

  // A chunk 0 -> regs -> smem
  float4 av0 = *(const float4*)(h_src + ae * 256 + ac);
  float4 av1 = *(const float4*)(h_src + ae * 256 + ac + 4);
  *(uint4*)(smem + SM_A0 + (ar * APAD + ac) * 2) = pack8(av0, av1);
  cp_wait0();
  __syncthreads();

  const char* Ab;
  const char* Bb;
  char* Hb = smem + SM_H;
  const int kq = (lane & 3) * 2;
  const int rb = lane >> 2;

  // ---- GEMM1: h = relu([h_src|h_dst] @ Wt^T + b), KC=32, 16 iters ----
  float acc[2][8][4];
#pragma unroll
  for (int a = 0; a < 2; a++)
#pragma unroll
    for (int b = 0; b < 8; b++)
#pragma unroll
      for (int c = 0; c < 4; c++) acc[a][b][c] = 0.f;

  for (int it = 0; it < 16; ++it) {
    const int cur = it & 1;
    // issue next B (or GEMM2 chunk 0 on the last iter) into the other buffer
    if (it + 1 < 16)
      cpB(su, cur ? SM_B0 : SM_B1, g_Wt, 512, (it + 1) * 32, tid);
    else
      cpB(su, SM_B0, g_Wp2, 256, 0, tid);
    cp_commit();
    // next A -> regs
    if (it + 1 < 16) {
      int kb = (it + 1) * 32;
      const float* ap = (kb < 256) ? (h_src + ae * 256 + kb) : (h_dst + ae * 256 + (kb - 256));
      av0 = *(const float4*)(ap + ac);
      av1 = *(const float4*)(ap + ac + 4);
    }
    // compute current
    Ab = smem + (cur ? SM_A1 : SM_A0);
    Bb = smem + (cur ? SM_B1 : SM_B0);
#pragma unroll
    for (int ks = 0; ks < 2; ++ks) {
      const int kk = ks * 16 + kq;
      uint32_t af[2][4];
#pragma unroll
      for (int mi = 0; mi < 2; ++mi) {
        int r = wm * 32 + mi * 16 + rb;
        af[mi][0] = *(const uint32_t*)(Ab + (r * APAD + kk) * 2);
        af[mi][1] = *(const uint32_t*)(Ab + ((r + 8) * APAD + kk) * 2);
        af[mi][2] = *(const uint32_t*)(Ab + (r * APAD + kk + 8) * 2);
        af[mi][3] = *(const uint32_t*)(Ab + ((r + 8) * APAD + kk + 8) * 2);
      }
#pragma unroll
      for (int ni = 0; ni < 8; ++ni) {
        int n = wn * 64 + ni * 8 + rb;
        uint32_t b0 = *(const uint32_t*)(Bb + (n * BPAD + kk) * 2);
        uint32_t b1 = *(const uint32_t*)(Bb + (n * BPAD + kk + 8) * 2);
        mma16816(acc[0][ni], af[0][0], af[0][1], af[0][2], af[0][3], b0, b1);
        mma16816(acc[1][ni], af[1][0], af[1][1], af[1][2], af[1][3], b0, b1);
      }
    }
    // store next A into the other buffer
    if (it + 1 < 16)
      *(uint4*)(smem + (cur ? SM_A0 : SM_A1) + (ar * APAD + ac) * 2) = pack8(av0, av1);
    cp_wait0();
    __syncthreads();
  }

  // epilogue: bias + relu -> h (bf16, HP-padded)
#pragma unroll
  for (int mi = 0; mi < 2; ++mi) {
    int r = wm * 32 + mi * 16 + rb;
#pragma unroll
    for (int ni = 0; ni < 8; ++ni) {
      int n0 = wn * 64 + ni * 8 + (lane & 3) * 2;
      float bb0 = bias[n0], bb1 = bias[n0 + 1];
      __nv_bfloat162 q0 = __floats2bfloat162_rn(fmaxf(acc[mi][ni][0] + bb0, 0.f),
                                                fmaxf(acc[mi][ni][1] + bb1, 0.f));
      __nv_bfloat162 q1 = __floats2bfloat162_rn(fmaxf(acc[mi][ni][2] + bb0, 0.f),
                                                fmaxf(acc[mi][ni][3] + bb1, 0.f));
      *(uint32_t*)(Hb + (r * HP + n0) * 2) = *(uint32_t*)&q0;
      *(uint32_t*)(Hb + ((r + 8) * HP + n0) * 2) = *(uint32_t*)&q1;
    }
  }
  __syncthreads();

  // ---- GEMM2: logits_all = h @ Wp2^T, KC=32, 8 iters (chunk 0 already landed in B0) ----
  float ac2[2][8][4];
#pragma unroll
  for (int a = 0; a < 2; a++)
#pragma unroll
    for (int b = 0; b < 8; b++)
#pragma unroll
      for (int c = 0; c < 4; c++) ac2[a][b][c] = 0.f;

  const __nv_bfloat16* Hh = (const __nv_bfloat16*)(smem + SM_H);
  for (int it = 0; it < 8; ++it) {
    const int cur = it & 1;
    if (it + 1 < 8) {
      cpB(su, cur ? SM_B0 : SM_B1, g_Wp2, 256, (it + 1) * 32, tid);
      cp_commit();
    }
    Bb = smem + (cur ? SM_B1 : SM_B0);
#pragma unroll
    for (int ks = 0; ks < 2; ++ks) {
      const int kk = ks * 16 + kq;
      const int kg = it * 32 + kk;
      uint32_t af[2][4];
#pragma unroll
      for (int mi = 0; mi < 2; ++mi) {
        int r = wm * 32 + mi * 16 + rb;
        af[mi][0] = *(const uint32_t*)(Hh + r * HP + kg);
        af[mi][1] = *(const uint32_t*)(Hh + (r + 8) * HP + kg);
        af[mi][2] = *(const uint32_t*)(Hh + r * HP + kg + 8);
        af[mi][3] = *(const uint32_t*)(Hh + (r + 8) * HP + kg + 8);
      }
#pragma unroll
      for (int ni = 0; ni < 8; ++ni) {
        int n = wn * 64 + ni * 8 + rb;
        uint32_t b0 = *(const uint32_t*)(Bb + (n * BPAD + kk) * 2);
        uint32_t b1 = *(const uint32_t*)(Bb + (n * BPAD + kk + 8) * 2);
        mma16816(ac2[0][ni], af[0][0], af[0][1], af[0][2], af[0][3], b0, b1);
        mma16816(ac2[1][ni], af[1][0], af[1][1], af[1][2], af[1][3], b0, b1);
      }
    }
    cp_wait0();
    __syncthreads();
  }

  // select each edge's pair columns into Lg
#pragma unroll
  for (int mi = 0; mi < 2; ++mi) {
    int r = wm * 32 + mi * 16 + rb;
    int plo = spair[r] * 16, phi = spair[r + 8] * 16;
#pragma unroll
    for (int ni = 0; ni < 8; ++ni) {
      int n0 = wn * 64 + ni * 8 + (lane & 3) * 2;
#pragma unroll
      for (int jj = 0; jj < 2; ++jj) {
        int c = n0 + jj;
        float bp = bpred[c];
        int cl = c - plo;
        if ((unsigned)cl < 16u) Lg[r * 17 + cl] = ac2[mi][ni][jj] + bp;
        int ch = c - phi;
        if ((unsigned)ch < 16u) Lg[(r + 8) * 17 + ch] = ac2[mi][ni][jj + 2] + bp;
      }
    }
  }
  __syncthreads();

  // per-edge softmax NLL + per-pair partials
  if (tid < 64) {
    long e = e0 + tid;
    if (e < E) {
      const float* L = Lg + tid * 17;
      float mx = -1e30f;
#pragma unroll
      for (int c = 0; c < 16; ++c) mx = fmaxf(mx, L[c]);
      float s = 0.f;
#pragma unroll
      for (int c = 0; c < 16; ++c) s += __expf(L[c] - mx);
      float l = __logf(s) + mx - L[slabel[tid]];
      atomicAdd(&psum[spair[tid]], l);
      atomicAdd(&pcnt[spair[tid]], 1);
    }
  }
  __syncthreads();
  if (tid < 16 && pcnt[tid] > 0) {
    atomicAdd(&g_sums[tid], psum[tid]);
    atomicAdd(&g_cnts[tid], (float)pcnt[tid]);
  }
  __threadfence();
  __syncthreads();
  if (tid == 0) {
    int prev = atomicAdd(&g_done, 1);
    if (prev == (int)gridDim.x - 1) {
      __threadfence();
      float ls = 0.f, np = 0.f;
#pragma unroll
      for (int p = 0; p < 16; ++p) {
        float c = g_cnts[p];
        if (c > 0.f) { ls += g_sums[p] / c; np += 1.f; }
      }
      out[0] = ls / np;
    }
  }
}

extern "C" void kernel_launch(void* const* d_in, const int* in_sizes, int n_in,
                              void* d_out, int out_size) {
  const float* h_src = (const float*)d_in[0];
  const float* h_dst = (const float*)d_in[1];
  const float* W1 = (const float*)d_in[2];
  const float* W2 = (const float*)d_in[3];
  const float* b_dec = (const float*)d_in[4];
  const float* W_pred = (const float*)d_in[5];
  const float* b_pred = (const float*)d_in[6];
  const int* st = (const int*)d_in[7];
  const int* dt = (const int*)d_in[8];
  const int* etc = (const int*)d_in[9];
  const int* em = (const int*)d_in[10];
  int E = in_sizes[7];

  cudaFuncSetAttribute(main_kernel, cudaFuncAttributeMaxDynamicSharedMemorySize, SMEM_TOTAL);
  prep_kernel<<<512, 256>>>(W1, W2, W_pred);
  int grid = (E + TM - 1) / TM;
  main_kernel<<<grid, THREADS, SMEM_TOTAL>>>(h_src, h_dst, b_dec, b_pred, st, dt, etc, em,
                                             (float*)d_out, E);
}

// round 9
// speedup vs baseline: 1.3922x; 1.3922x over previous
#include <cuda_runtime.h>
#include <cuda_bf16.h>
#include <stdint.h>

#define TM 128
#define THREADS 512
#define APAD 40
#define BPAD 40
#define HP 264

// device scratch
__device__ __align__(16) __nv_bfloat16 g_Wt[256 * 512];   // [n][k] decoder weights, bf16
__device__ __align__(16) __nv_bfloat16 g_Wp2[256 * 256];  // [p*16+c][k] head weights, bf16
__device__ float g_sums[16];
__device__ float g_cnts[16];
__device__ int g_done;

struct SmemT {
  __nv_bfloat16 As[2][128 * APAD];  // A k-chunk, double buffered (KC=32)
  __nv_bfloat16 Bs[2][256 * BPAD];  // B k-chunk, double buffered (KC=32)
  __nv_bfloat16 h[128 * HP];        // activations tile, bf16
  float Lg[128 * 17];               // selected logits (raw, bias added later)
  float bias[256];
  float bpred[256];
  int em[16 * 24];
  int spair[128];
  int slabel[128];
  float psum[16];
  int pcnt[16];
  int cnt[16];
  int offp[16];
  int cur[16];
  int bucket[128];
};

__global__ void prep_kernel(const float* __restrict__ W1, const float* __restrict__ W2,
                            const float* __restrict__ Wp) {
  int i = blockIdx.x * blockDim.x + threadIdx.x;
  if (i < 256 * 512) {
    int n = i >> 9, k = i & 511;
    float v = (k < 256) ? W1[k * 256 + n] : W2[(k - 256) * 256 + n];
    g_Wt[n * 512 + k] = __float2bfloat16(v);
  }
  if (i < 256 * 256) {
    int col = i >> 8, k = i & 255;
    int p = col >> 4, c = col & 15;
    g_Wp2[col * 256 + k] = __float2bfloat16(Wp[p * 4096 + k * 16 + c]);
  }
  if (i < 16) { g_sums[i] = 0.f; g_cnts[i] = 0.f; }
  if (i == 0) g_done = 0;
}

__device__ __forceinline__ void mma16816(float* c, uint32_t a0, uint32_t a1, uint32_t a2,
                                         uint32_t a3, uint32_t b0, uint32_t b1) {
  asm volatile(
      "mma.sync.aligned.m16n8k16.row.col.f32.bf16.bf16.f32 "
      "{%0,%1,%2,%3}, {%4,%5,%6,%7}, {%8,%9}, {%0,%1,%2,%3};\n"
      : "+f"(c[0]), "+f"(c[1]), "+f"(c[2]), "+f"(c[3])
      : "r"(a0), "r"(a1), "r"(a2), "r"(a3), "r"(b0), "r"(b1));
}

__device__ __forceinline__ uint4 pack8(float4 a, float4 b) {
  __nv_bfloat162 p0 = __floats2bfloat162_rn(a.x, a.y);
  __nv_bfloat162 p1 = __floats2bfloat162_rn(a.z, a.w);
  __nv_bfloat162 p2 = __floats2bfloat162_rn(b.x, b.y);
  __nv_bfloat162 p3 = __floats2bfloat162_rn(b.z, b.w);
  uint4 u;
  u.x = *(uint32_t*)&p0; u.y = *(uint32_t*)&p1;
  u.z = *(uint32_t*)&p2; u.w = *(uint32_t*)&p3;
  return u;
}

__global__ __launch_bounds__(THREADS, 1)
void main_kernel(const float* __restrict__ h_src, const float* __restrict__ h_dst,
                 const float* __restrict__ b_dec, const float* __restrict__ b_pred,
                 const int* __restrict__ st, const int* __restrict__ dt,
                 const int* __restrict__ etc, const int* __restrict__ emap,
                 float* __restrict__ out, int E) {
  extern __shared__ __align__(16) char smem_raw[];
  SmemT* S = (SmemT*)smem_raw;
  const int tid = threadIdx.x;
  const int warp = tid >> 5, lane = tid & 31;
  const int wm = warp & 3, wn = warp >> 2;
  const long e0 = (long)blockIdx.x * TM;
  const int kq = (lane & 3) * 2;
  const int rb = lane >> 2;

  for (int i = tid; i < 256; i += THREADS) { S->bias[i] = b_dec[i]; S->bpred[i] = b_pred[i]; }
  for (int i = tid; i < 384; i += THREADS) S->em[i] = emap[i];
  if (tid < 16) { S->psum[tid] = 0.f; S->pcnt[tid] = 0; S->cnt[tid] = 0; }
  __syncthreads();
  if (tid < 128) {
    long e = e0 + tid; if (e >= E) e = E - 1;
    int p = st[e] * 4 + dt[e];
    S->spair[tid] = p;
    S->slabel[tid] = S->em[p * 24 + etc[e]];
    atomicAdd(&S->cnt[p], 1);
  }
  __syncthreads();
  if (tid == 0) {
    int a = 0;
#pragma unroll
    for (int p = 0; p < 16; ++p) { S->offp[p] = a; S->cur[p] = a; a += S->cnt[p]; }
  }
  __syncthreads();
  if (tid < 128) {
    int pos = atomicAdd(&S->cur[S->spair[tid]], 1);
    S->bucket[pos] = tid;
  }

  // ---- GEMM1: h = relu([h_src|h_dst] @ Wt^T + b), KC=32 double-buffered ----
  float acc[2][8][4];
#pragma unroll
  for (int a = 0; a < 2; a++)
#pragma unroll
    for (int b = 0; b < 8; b++)
#pragma unroll
      for (int c = 0; c < 4; c++) acc[a][b][c] = 0.f;

  const int ar = tid >> 2, ac = (tid & 3) * 8;   // A: 128 rows x 32 k, 8 floats/thread
  long ae = e0 + ar; if (ae >= E) ae = E - 1;
  const int bn = tid >> 1, bh = (tid & 1) * 16;  // B: 256 rows x 32 k, 16 bf16/thread

  const float* apA = h_src + ae * 256;
  float4 av0 = *(const float4*)(apA + ac);
  float4 av1 = *(const float4*)(apA + ac + 4);
  uint4 bv0 = *(const uint4*)(g_Wt + bn * 512 + bh);
  uint4 bv1 = *(const uint4*)(g_Wt + bn * 512 + bh + 8);

  *(uint4*)(&S->As[0][ar * APAD + ac]) = pack8(av0, av1);
  *(uint4*)(&S->Bs[0][bn * BPAD + bh]) = bv0;
  *(uint4*)(&S->Bs[0][bn * BPAD + bh + 8]) = bv1;
  __syncthreads();

  for (int it = 0; it < 16; ++it) {
    const int cur = it & 1;
    const bool more = (it + 1 < 16);
    if (more) {
      int kb = (it + 1) * 32;
      const float* ap = (kb < 256) ? (h_src + ae * 256 + kb) : (h_dst + ae * 256 + (kb - 256));
      av0 = *(const float4*)(ap + ac);
      av1 = *(const float4*)(ap + ac + 4);
      bv0 = *(const uint4*)(g_Wt + bn * 512 + kb + bh);
      bv1 = *(const uint4*)(g_Wt + bn * 512 + kb + bh + 8);
    }
    const __nv_bfloat16* Ab = S->As[cur];
    const __nv_bfloat16* Bb = S->Bs[cur];
#pragma unroll
    for (int ks = 0; ks < 2; ++ks) {
      const int kk = ks * 16 + kq;
      uint32_t af[2][4];
#pragma unroll
      for (int mi = 0; mi < 2; ++mi) {
        int r = wm * 32 + mi * 16 + rb;
        af[mi][0] = *(const uint32_t*)(Ab + r * APAD + kk);
        af[mi][1] = *(const uint32_t*)(Ab + (r + 8) * APAD + kk);
        af[mi][2] = *(const uint32_t*)(Ab + r * APAD + kk + 8);
        af[mi][3] = *(const uint32_t*)(Ab + (r + 8) * APAD + kk + 8);
      }
#pragma unroll
      for (int ni = 0; ni < 8; ++ni) {
        int n = wn * 64 + ni * 8 + rb;
        uint32_t b0 = *(const uint32_t*)(Bb + n * BPAD + kk);
        uint32_t b1 = *(const uint32_t*)(Bb + n * BPAD + kk + 8);
        mma16816(acc[0][ni], af[0][0], af[0][1], af[0][2], af[0][3], b0, b1);
        mma16816(acc[1][ni], af[1][0], af[1][1], af[1][2], af[1][3], b0, b1);
      }
    }
    if (more) {
      *(uint4*)(&S->As[cur ^ 1][ar * APAD + ac]) = pack8(av0, av1);
      *(uint4*)(&S->Bs[cur ^ 1][bn * BPAD + bh]) = bv0;
      *(uint4*)(&S->Bs[cur ^ 1][bn * BPAD + bh + 8]) = bv1;
    }
    __syncthreads();
  }

  // epilogue: bias + relu -> h (bf16 in smem)
  char* Hb = (char*)S->h;
#pragma unroll
  for (int mi = 0; mi < 2; ++mi) {
    int r = wm * 32 + mi * 16 + rb;
#pragma unroll
    for (int ni = 0; ni < 8; ++ni) {
      int n0 = wn * 64 + ni * 8 + (lane & 3) * 2;
      float bb0 = S->bias[n0], bb1 = S->bias[n0 + 1];
      __nv_bfloat162 q0 = __floats2bfloat162_rn(fmaxf(acc[mi][ni][0] + bb0, 0.f),
                                                fmaxf(acc[mi][ni][1] + bb1, 0.f));
      __nv_bfloat162 q1 = __floats2bfloat162_rn(fmaxf(acc[mi][ni][2] + bb0, 0.f),
                                                fmaxf(acc[mi][ni][3] + bb1, 0.f));
      *(uint32_t*)(Hb + (r * HP + n0) * 2) = *(uint32_t*)&q0;
      *(uint32_t*)(Hb + ((r + 8) * HP + n0) * 2) = *(uint32_t*)&q1;
    }
  }
  __syncthreads();

  // ---- GEMM2 (bucketed): warp w handles pair w; only the selected head ----
  {
    const int p = warp;
    const int m = S->cnt[p];
    const int off = S->offp[p];
    const __nv_bfloat16* Hh = S->h;
    const __nv_bfloat16* Wb = g_Wp2 + (p * 16) * 256;  // 16 cols x 256 k, L2-hot
    for (int t = 0; t * 16 < m; ++t) {
      int i0 = t * 16 + rb, i1 = i0 + 8;
      int r0 = (i0 < m) ? S->bucket[off + i0] : S->bucket[off];
      int r1 = (i1 < m) ? S->bucket[off + i1] : S->bucket[off];
      float a0[4] = {0.f, 0.f, 0.f, 0.f};
      float a1[4] = {0.f, 0.f, 0.f, 0.f};
#pragma unroll 4
      for (int ks = 0; ks < 16; ++ks) {
        int kk = ks * 16 + kq;
        uint32_t f0 = *(const uint32_t*)(Hh + r0 * HP + kk);
        uint32_t f1 = *(const uint32_t*)(Hh + r1 * HP + kk);
        uint32_t f2 = *(const uint32_t*)(Hh + r0 * HP + kk + 8);
        uint32_t f3 = *(const uint32_t*)(Hh + r1 * HP + kk + 8);
        uint32_t b0 = *(const uint32_t*)(Wb + rb * 256 + kk);
        uint32_t b1 = *(const uint32_t*)(Wb + rb * 256 + kk + 8);
        uint32_t b2 = *(const uint32_t*)(Wb + (8 + rb) * 256 + kk);
        uint32_t b3 = *(const uint32_t*)(Wb + (8 + rb) * 256 + kk + 8);
        mma16816(a0, f0, f1, f2, f3, b0, b1);
        mma16816(a1, f0, f1, f2, f3, b2, b3);
      }
      // scatter logits: cols (lane&3)*2+{0,1} (+8 for a1); rows r0 (c01), r1 (c23)
      int c0 = (lane & 3) * 2;
      if (i0 < m) {
        S->Lg[r0 * 17 + c0] = a0[0];
        S->Lg[r0 * 17 + c0 + 1] = a0[1];
        S->Lg[r0 * 17 + 8 + c0] = a1[0];
        S->Lg[r0 * 17 + 8 + c0 + 1] = a1[1];
      }
      if (i1 < m) {
        S->Lg[r1 * 17 + c0] = a0[2];
        S->Lg[r1 * 17 + c0 + 1] = a0[3];
        S->Lg[r1 * 17 + 8 + c0] = a1[2];
        S->Lg[r1 * 17 + 8 + c0 + 1] = a1[3];
      }
    }
  }
  __syncthreads();

  // per-edge softmax NLL + per-pair partials
  if (tid < 128) {
    long e = e0 + tid;
    if (e < E) {
      const float* L = S->Lg + tid * 17;
      const float* bp = S->bpred + S->spair[tid] * 16;
      float mx = -1e30f;
      float Lb[16];
#pragma unroll
      for (int c = 0; c < 16; ++c) { Lb[c] = L[c] + bp[c]; mx = fmaxf(mx, Lb[c]); }
      float s = 0.f;
#pragma unroll
      for (int c = 0; c < 16; ++c) s += __expf(Lb[c] - mx);
      float l = __logf(s) + mx - Lb[S->slabel[tid]];
      atomicAdd(&S->psum[S->spair[tid]], l);
      atomicAdd(&S->pcnt[S->spair[tid]], 1);
    }
  }
  __syncthreads();
  if (tid < 16 && S->pcnt[tid] > 0) {
    atomicAdd(&g_sums[tid], S->psum[tid]);
    atomicAdd(&g_cnts[tid], (float)S->pcnt[tid]);
  }
  __threadfence();
  __syncthreads();
  if (tid == 0) {
    int prev = atomicAdd(&g_done, 1);
    if (prev == (int)gridDim.x - 1) {
      __threadfence();
      float ls = 0.f, np = 0.f;
#pragma unroll
      for (int p = 0; p < 16; ++p) {
        float c = g_cnts[p];
        if (c > 0.f) { ls += g_sums[p] / c; np += 1.f; }
      }
      out[0] = ls / np;
    }
  }
}

extern "C" void kernel_launch(void* const* d_in, const int* in_sizes, int n_in,
                              void* d_out, int out_size) {
  const float* h_src = (const float*)d_in[0];
  const float* h_dst = (const float*)d_in[1];
  const float* W1 = (const float*)d_in[2];
  const float* W2 = (const float*)d_in[3];
  const float* b_dec = (const float*)d_in[4];
  const float* W_pred = (const float*)d_in[5];
  const float* b_pred = (const float*)d_in[6];
  const int* st = (const int*)d_in[7];
  const int* dt = (const int*)d_in[8];
  const int* etc = (const int*)d_in[9];
  const int* em = (const int*)d_in[10];
  int E = in_sizes[7];

  cudaFuncSetAttribute(main_kernel, cudaFuncAttributeMaxDynamicSharedMemorySize,
                       (int)sizeof(SmemT));
  prep_kernel<<<512, 256>>>(W1, W2, W_pred);
  int grid = (E + TM - 1) / TM;
  main_kernel<<<grid, THREADS, sizeof(SmemT)>>>(h_src, h_dst, b_dec, b_pred, st, dt, etc, em,
                                                (float*)d_out, E);
}